// round 14
// baseline (speedup 1.0000x reference)
#include <cuda_runtime.h>
#include <cuda_fp16.h>
#include <cstdint>

#define NN   50000
#define EE   800000
#define HIN  256
#define HH   128
#define BNEPS 1e-5f

// ---------------- device scratch ----------------
__device__ int    g_degr[NN];
__device__ int    g_cnt[NN];
__device__ int    g_cursor[NN];
__device__ int    g_startv[NN + 1];
__device__ int    g_csr_rows[EE];
__device__ float  g_dinv[NN];
__device__ __half g_s[(size_t)NN * HH];      // pre-aggregation messages (fp16, dinv-scaled)
__device__ __half g_ah[(size_t)NN * HIN];    // A operand hi (fp16)
__device__ __half g_al[(size_t)NN * HIN];    // A operand lo (fp16)
__device__ __half g_w16[HH * HIN];           // folded weight fp16, [n][k] K-major
__device__ float  g_sum[HIN];
__device__ float  g_sumsq[HIN];
__device__ float  g_bshift[HH];

// ---------------- PTX helpers (baseline sm_80+ only) ----------------
__device__ __forceinline__ uint32_t smem_u32(const void* p) {
    uint32_t a;
    asm("{ .reg .u64 t; cvta.to.shared.u64 t, %1; cvt.u32.u64 %0, t; }" : "=r"(a) : "l"(p));
    return a;
}
#define CP16(dst, src) \
    asm volatile("cp.async.cg.shared.global [%0], [%1], 16;" :: "r"(dst), "l"(src))
#define CP_COMMIT() asm volatile("cp.async.commit_group;" ::: "memory")
#define CP_WAIT2()  asm volatile("cp.async.wait_group 2;" ::: "memory")
#define LDSM_X4(r, addr) \
    asm volatile("ldmatrix.sync.aligned.m8n8.x4.shared.b16 {%0,%1,%2,%3}, [%4];" \
        : "=r"((r)[0]), "=r"((r)[1]), "=r"((r)[2]), "=r"((r)[3]) : "r"(addr))
#define MMA_F16(c, a, b) \
    asm volatile("mma.sync.aligned.m16n8k16.row.col.f32.f16.f16.f32 " \
        "{%0,%1,%2,%3}, {%4,%5,%6,%7}, {%8,%9}, {%0,%1,%2,%3};" \
        : "+f"((c)[0]), "+f"((c)[1]), "+f"((c)[2]), "+f"((c)[3]) \
        : "r"((a)[0]), "r"((a)[1]), "r"((a)[2]), "r"((a)[3]), "r"((b)[0]), "r"((b)[1]))

// ---------------- CSR build ----------------
__global__ void k_count(const int* __restrict__ ei) {
    int e = blockIdx.x * blockDim.x + threadIdx.x;
    if (e < EE) {
        atomicAdd(&g_degr[ei[e]], 1);
        atomicAdd(&g_cnt[ei[EE + e]], 1);
    }
}
// scan + dinv (dinv needs completed g_degr; free ride on this 1-block kernel)
__global__ void k_scan() {
    __shared__ int part[1024];
    int t = threadIdx.x;
    const int per = (NN + 1023) / 1024;
    int b = t * per, e = min(b + per, NN);
    int s = 0;
    for (int i = b; i < e; i++) s += g_cnt[i];
    part[t] = s;
    __syncthreads();
    for (int off = 1; off < 1024; off <<= 1) {
        int v = (t >= off) ? part[t - off] : 0;
        __syncthreads();
        part[t] += v;
        __syncthreads();
    }
    int base = (t == 0) ? 0 : part[t - 1];
    for (int i = b; i < e; i++) { g_startv[i] = base; base += g_cnt[i]; }
    if (t == 1023) g_startv[NN] = part[1023];
    for (int i = b; i < e; i++)
        g_dinv[i] = rsqrtf((float)g_degr[i] + 1.0f);
}
__global__ void k_fill(const int* __restrict__ ei) {
    int e = blockIdx.x * blockDim.x + threadIdx.x;
    if (e < EE) {
        int r = ei[e], c = ei[EE + e];
        int p = atomicAdd(&g_cursor[c], 1);
        g_csr_rows[g_startv[c] + p] = r;
    }
}

// ---------------- fused: convert x -> fp16 hi/lo, BN col stats, zero CSR arrays ----------------
__global__ void __launch_bounds__(256) k_convx_stats(const float* __restrict__ x) {
    __shared__ float sS[HIN], sQ[HIN];
    const int t = threadIdx.x;              // 256
    sS[t] = 0.f; sQ[t] = 0.f;
    __syncthreads();

    const int col = (t & 63) * 4;           // fixed 4 columns per thread
    const int ro  = t >> 6;                 // row offset 0..3
    float s0 = 0.f, s1 = 0.f, s2 = 0.f, s3 = 0.f;
    float q0 = 0.f, q1 = 0.f, q2 = 0.f, q3 = 0.f;

    for (int r0 = blockIdx.x * 4; r0 < NN; r0 += gridDim.x * 4) {
        int r = r0 + ro;                    // NN % 4 == 0 -> always < NN
        size_t idx = (size_t)r * HIN + col;
        float4 v = *(const float4*)(x + idx);
        __half h0 = __float2half_rn(v.x), h1 = __float2half_rn(v.y);
        __half h2 = __float2half_rn(v.z), h3 = __float2half_rn(v.w);
        uint2 uh, ul;
        *(__half2*)&uh.x = __halves2half2(h0, h1);
        *(__half2*)&uh.y = __halves2half2(h2, h3);
        *(__half2*)&ul.x = __floats2half2_rn(v.x - __half2float(h0), v.y - __half2float(h1));
        *(__half2*)&ul.y = __floats2half2_rn(v.z - __half2float(h2), v.w - __half2float(h3));
        *(uint2*)(g_ah + idx) = uh;
        *(uint2*)(g_al + idx) = ul;
        s0 += v.x; q0 += v.x * v.x;
        s1 += v.y; q1 += v.y * v.y;
        s2 += v.z; q2 += v.z * v.z;
        s3 += v.w; q3 += v.w * v.w;
    }
    atomicAdd(&sS[col + 0], s0); atomicAdd(&sQ[col + 0], q0);
    atomicAdd(&sS[col + 1], s1); atomicAdd(&sQ[col + 1], q1);
    atomicAdd(&sS[col + 2], s2); atomicAdd(&sQ[col + 2], q2);
    atomicAdd(&sS[col + 3], s3); atomicAdd(&sQ[col + 3], q3);
    __syncthreads();
    atomicAdd(&g_sum[t], sS[t]);
    atomicAdd(&g_sumsq[t], sQ[t]);

    // fused zeroing of CSR count arrays
    for (int i = blockIdx.x * blockDim.x + t; i < NN; i += gridDim.x * blockDim.x) {
        g_degr[i] = 0; g_cnt[i] = 0; g_cursor[i] = 0;
    }
}

// ---------------- fold BN into weights; emit fp16 W^T + fp32 bshift ----------------
__global__ void k_fold(int K, const float* __restrict__ W,
                       const float* __restrict__ gam, const float* __restrict__ bet) {
    __shared__ float sc[HIN], sh[HIN];
    int t = threadIdx.x;             // 256 threads
    if (t < K) {
        float mu  = g_sum[t] * (1.0f / NN);
        float var = g_sumsq[t] * (1.0f / NN) - mu * mu;
        float a   = rsqrtf(var + BNEPS) * gam[t];
        sc[t] = a;
        sh[t] = bet[t] - mu * a;
    }
    __syncthreads();
    for (int idx = t; idx < K * HH; idx += 256) {
        int k = idx >> 7;            // W row
        int n = idx & 127;           // W col
        g_w16[(size_t)n * K + k] = __float2half_rn(sc[k] * W[idx]);
    }
    if (t < HH) {
        float acc = 0.f;
        for (int k = 0; k < K; k++) acc += sh[k] * W[k * HH + t];
        g_bshift[t] = acc;
    }
    g_sum[t] = 0.f;
    g_sumsq[t] = 0.f;
}

// ---------------- 2-term fp16 HMMA GEMM, 3-stage cp.async pipeline ----------------
// g_s(fp16) = ((Ah + Al) @ W16^T + bshift) * dinv[row]
#define RS   48
#define TSZ  (128 * RS)          // 6144 bytes per tile
#define STG  (3 * TSZ)           // 18432 bytes per stage
#define NSTG 3

__global__ void __launch_bounds__(256) k_gemm_h(int K) {
    extern __shared__ char smem[];
    const int t    = threadIdx.x;
    const int wid  = t >> 5;
    const int lane = t & 31;
    const int wm   = wid & 3;          // 32-row band
    const int wn   = wid >> 2;         // 64-col band
    const int row0 = blockIdx.x * 128;
    const uint32_t sbase = smem_u32(smem);

    float c[2][8][4];
    #pragma unroll
    for (int mt = 0; mt < 2; mt++)
        #pragma unroll
        for (int nt = 0; nt < 8; nt++)
            #pragma unroll
            for (int q = 0; q < 4; q++) c[mt][nt][q] = 0.f;

    const int lr = t >> 1;
    const int lh = t & 1;
    const int ar = min(row0 + lr, NN - 1);
    const uint32_t so = lr * RS + lh * 16;
    const int nch = K >> 4;            // >= 8 always

    // prologue: chunks 0,1 -> stages 0,1
    #pragma unroll
    for (int pc = 0; pc < 2; pc++) {
        uint32_t sb = sbase + pc * STG;
        size_t ka = (size_t)ar * K + pc * 16 + lh * 8;
        size_t kb = (size_t)lr * K + pc * 16 + lh * 8;
        CP16(sb + 0 * TSZ + so, g_ah + ka);
        CP16(sb + 1 * TSZ + so, g_al + ka);
        CP16(sb + 2 * TSZ + so, g_w16 + kb);
        CP_COMMIT();
    }

    int stage = 0;
    for (int kc = 0; kc < nch; kc++) {
        int pf = kc + 2;
        if (pf < nch) {
            int ps = pf % NSTG;
            uint32_t sb = sbase + ps * STG;
            size_t ka = (size_t)ar * K + pf * 16 + lh * 8;
            size_t kb = (size_t)lr * K + pf * 16 + lh * 8;
            CP16(sb + 0 * TSZ + so, g_ah + ka);
            CP16(sb + 1 * TSZ + so, g_al + ka);
            CP16(sb + 2 * TSZ + so, g_w16 + kb);
        }
        CP_COMMIT();
        CP_WAIT2();                    // chunk kc's group complete
        __syncthreads();

        uint32_t base = sbase + stage * STG;
        uint32_t ah[2][4], al[2][4];
        #pragma unroll
        for (int mt = 0; mt < 2; mt++) {
            uint32_t addr = base + (wm * 32 + mt * 16 + (lane & 15)) * RS + (lane >> 4) * 16;
            LDSM_X4(ah[mt], addr);
            LDSM_X4(al[mt], addr + TSZ);
        }
        uint32_t bw[8][2];
        #pragma unroll
        for (int p = 0; p < 4; p++) {
            uint32_t addr = base + 2 * TSZ + (wn * 64 + p * 16 + (lane & 15)) * RS + (lane >> 4) * 16;
            uint32_t rr[4];
            LDSM_X4(rr, addr);
            bw[2 * p][0] = rr[0]; bw[2 * p][1] = rr[2];
            bw[2 * p + 1][0] = rr[1]; bw[2 * p + 1][1] = rr[3];
        }
        #pragma unroll
        for (int mt = 0; mt < 2; mt++)
            #pragma unroll
            for (int nt = 0; nt < 8; nt++) {
                MMA_F16(c[mt][nt], ah[mt], bw[nt]);
                MMA_F16(c[mt][nt], al[mt], bw[nt]);
            }
        __syncthreads();               // protect stage reuse by next prefetch
        stage = (stage + 1) % NSTG;
    }

    // epilogue: (acc + bshift[col]) * dinv[row] -> fp16 g_s
    float bsv[8][2];
    #pragma unroll
    for (int nt = 0; nt < 8; nt++) {
        int gc = wn * 64 + nt * 8 + (lane & 3) * 2;
        bsv[nt][0] = __ldg(&g_bshift[gc]);
        bsv[nt][1] = __ldg(&g_bshift[gc + 1]);
    }
    #pragma unroll
    for (int mt = 0; mt < 2; mt++) {
        int r0g = row0 + wm * 32 + mt * 16 + (lane >> 2);
        int r1g = r0g + 8;
        float dv0 = g_dinv[min(r0g, NN - 1)];
        float dv1 = g_dinv[min(r1g, NN - 1)];
        #pragma unroll
        for (int nt = 0; nt < 8; nt++) {
            int gc = wn * 64 + nt * 8 + (lane & 3) * 2;
            if (r0g < NN)
                *(__half2*)(g_s + (size_t)r0g * HH + gc) =
                    __floats2half2_rn((c[mt][nt][0] + bsv[nt][0]) * dv0,
                                      (c[mt][nt][1] + bsv[nt][1]) * dv0);
            if (r1g < NN)
                *(__half2*)(g_s + (size_t)r1g * HH + gc) =
                    __floats2half2_rn((c[mt][nt][2] + bsv[nt][0]) * dv1,
                                      (c[mt][nt][3] + bsv[nt][1]) * dv1);
        }
    }
}

// ---------------- gather: warp-per-node, HADD2 pair-tree, index prefetch ----------------
__global__ void __launch_bounds__(256) k_gather(const float* __restrict__ bgcn,
                                                float* __restrict__ out, int final_layer) {
    const int lane = threadIdx.x & 31;
    const int wg   = (blockIdx.x * blockDim.x + threadIdx.x) >> 5;
    const int nw   = (gridDim.x * blockDim.x) >> 5;
    __shared__ float sS[128], sQ[128];
    if (threadIdx.x < 128) { sS[threadIdx.x] = 0.f; sQ[threadIdx.x] = 0.f; }
    __syncthreads();

    const uint2* __restrict__ s2 = (const uint2*)g_s;   // 32 uint2 per node row
    float4 b = *(const float4*)(bgcn + lane * 4);
    float4 stS = make_float4(0.f, 0.f, 0.f, 0.f);
    float4 stQ = make_float4(0.f, 0.f, 0.f, 0.f);

    for (int node = wg; node < NN; node += nw) {
        uint2 vs = s2[(size_t)node * 32 + lane];        // self-loop (dinv-scaled)
        float2 f0 = __half22float2(*(__half2*)&vs.x);
        float2 f1 = __half22float2(*(__half2*)&vs.y);
        float a0 = f0.x, a1 = f0.y, a2 = f1.x, a3 = f1.y;

        int beg = g_startv[node];
        int end = g_startv[node + 1];
        int k = beg;
        int n0 = 0, n1 = 0, n2 = 0, n3 = 0;
        if (k + 3 < end) {
            n0 = __ldg(&g_csr_rows[k]);
            n1 = __ldg(&g_csr_rows[k + 1]);
            n2 = __ldg(&g_csr_rows[k + 2]);
            n3 = __ldg(&g_csr_rows[k + 3]);
        }
        for (; k + 3 < end; ) {
            int r0 = n0, r1 = n1, r2 = n2, r3 = n3;
            int kn = k + 4;
            if (kn + 3 < end) {        // prefetch next iteration's indices
                n0 = __ldg(&g_csr_rows[kn]);
                n1 = __ldg(&g_csr_rows[kn + 1]);
                n2 = __ldg(&g_csr_rows[kn + 2]);
                n3 = __ldg(&g_csr_rows[kn + 3]);
            }
            uint2 v0 = s2[(size_t)r0 * 32 + lane];
            uint2 v1 = s2[(size_t)r1 * 32 + lane];
            uint2 v2 = s2[(size_t)r2 * 32 + lane];
            uint2 v3 = s2[(size_t)r3 * 32 + lane];
            __half2 p0 = __hadd2(*(__half2*)&v0.x, *(__half2*)&v1.x);
            __half2 p1 = __hadd2(*(__half2*)&v0.y, *(__half2*)&v1.y);
            __half2 p2 = __hadd2(*(__half2*)&v2.x, *(__half2*)&v3.x);
            __half2 p3 = __hadd2(*(__half2*)&v2.y, *(__half2*)&v3.y);
            float2 q;
            q = __half22float2(p0); a0 += q.x; a1 += q.y;
            q = __half22float2(p1); a2 += q.x; a3 += q.y;
            q = __half22float2(p2); a0 += q.x; a1 += q.y;
            q = __half22float2(p3); a2 += q.x; a3 += q.y;
            k = kn;
        }
        if (k + 1 < end) {
            int r0 = __ldg(&g_csr_rows[k]);
            int r1 = __ldg(&g_csr_rows[k + 1]);
            uint2 v0 = s2[(size_t)r0 * 32 + lane];
            uint2 v1 = s2[(size_t)r1 * 32 + lane];
            __half2 p0 = __hadd2(*(__half2*)&v0.x, *(__half2*)&v1.x);
            __half2 p1 = __hadd2(*(__half2*)&v0.y, *(__half2*)&v1.y);
            float2 q;
            q = __half22float2(p0); a0 += q.x; a1 += q.y;
            q = __half22float2(p1); a2 += q.x; a3 += q.y;
            k += 2;
        }
        if (k < end) {
            int r0 = __ldg(&g_csr_rows[k]);
            uint2 v0 = s2[(size_t)r0 * 32 + lane];
            float2 q;
            q = __half22float2(*(__half2*)&v0.x); a0 += q.x; a1 += q.y;
            q = __half22float2(*(__half2*)&v0.y); a2 += q.x; a3 += q.y;
        }

        float dvn = g_dinv[node];
        float4 o;
        o.x = a0 * dvn + b.x;
        o.y = a1 * dvn + b.y;
        o.z = a2 * dvn + b.z;
        o.w = a3 * dvn + b.w;

        if (final_layer) {
            *(float4*)(out + (size_t)node * HH + lane * 4) = o;
        } else {
            __half h0 = __float2half_rn(o.x), h1 = __float2half_rn(o.y);
            __half h2 = __float2half_rn(o.z), h3 = __float2half_rn(o.w);
            size_t base = (size_t)node * HH + lane * 4;
            uint2 uh, ul;
            *(__half2*)&uh.x = __halves2half2(h0, h1);
            *(__half2*)&uh.y = __halves2half2(h2, h3);
            *(__half2*)&ul.x = __floats2half2_rn(o.x - __half2float(h0), o.y - __half2float(h1));
            *(__half2*)&ul.y = __floats2half2_rn(o.z - __half2float(h2), o.w - __half2float(h3));
            *(uint2*)(g_ah + base) = uh;
            *(uint2*)(g_al + base) = ul;
            stS.x += o.x; stS.y += o.y; stS.z += o.z; stS.w += o.w;
            stQ.x += o.x * o.x; stQ.y += o.y * o.y;
            stQ.z += o.z * o.z; stQ.w += o.w * o.w;
        }
    }

    if (!final_layer) {
        atomicAdd(&sS[lane * 4 + 0], stS.x);
        atomicAdd(&sS[lane * 4 + 1], stS.y);
        atomicAdd(&sS[lane * 4 + 2], stS.z);
        atomicAdd(&sS[lane * 4 + 3], stS.w);
        atomicAdd(&sQ[lane * 4 + 0], stQ.x);
        atomicAdd(&sQ[lane * 4 + 1], stQ.y);
        atomicAdd(&sQ[lane * 4 + 2], stQ.z);
        atomicAdd(&sQ[lane * 4 + 3], stQ.w);
        __syncthreads();
        if (threadIdx.x < 128) {
            atomicAdd(&g_sum[threadIdx.x], sS[threadIdx.x]);
            atomicAdd(&g_sumsq[threadIdx.x], sQ[threadIdx.x]);
        }
    }
}

// ---------------- launch ----------------
extern "C" void kernel_launch(void* const* d_in, const int* in_sizes, int n_in,
                              void* d_out, int out_size) {
    const float* x       = (const float*)d_in[0];
    const int*   ei      = (const int*)  d_in[1];
    const float* bnf_g   = (const float*)d_in[2];
    const float* bnf_b   = (const float*)d_in[3];
    const float* W_feat  = (const float*)d_in[4];
    const float* b_feat  = (const float*)d_in[5];
    const float* bn_g    = (const float*)d_in[6];
    const float* bn_b    = (const float*)d_in[7];
    const float* Ws      = (const float*)d_in[8];
    const float* bs      = (const float*)d_in[9];
    float* out = (float*)d_out;

    const int RB = (NN + 127) / 128;              // 391 tiles
    const int GB = 1563;                          // gather: ~12.5k warps
    const int EB = (EE + 255) / 256;
    const int GSM = NSTG * STG;                   // 55296 B dynamic smem

    cudaFuncSetAttribute(k_gemm_h, cudaFuncAttributeMaxDynamicSharedMemorySize, GSM);

    k_convx_stats<<<RB, 256>>>(x);                   // 0: x->fp16 hi/lo + stats + zero CSR
    k_count<<<EB, 256>>>(ei);                        // 1
    k_fold<<<1, 256>>>(HIN, W_feat, bnf_g, bnf_b);   // 2
    k_scan<<<1, 1024>>>();                           // 3 (scan + dinv)
    k_gemm_h<<<RB, 256, GSM>>>(HIN);                 // 4
    k_fill<<<EB, 256>>>(ei);                         // 5
    k_gather<<<GB, 256>>>(b_feat, nullptr, 0);       // 6

    // 3 GCN layers, K=128
    for (int i = 0; i < 3; i++) {
        k_fold<<<1, 256>>>(HH, Ws + (size_t)i * HH * HH, bn_g + i * HH, bn_b + i * HH);
        k_gemm_h<<<RB, 256, GSM>>>(HH);
        k_gather<<<GB, 256>>>(bs + i * HH, (i == 2) ? out : nullptr, (i == 2) ? 1 : 0);
    }
}

// round 15
// speedup vs baseline: 1.2045x; 1.2045x over previous
#include <cuda_runtime.h>
#include <cuda_fp16.h>
#include <cstdint>

#define NN   50000
#define EE   800000
#define HIN  256
#define HH   128
#define BNEPS 1e-5f
#define NB   196                 // ceil(NN/256)

// ---------------- device scratch ----------------
__device__ int    g_degr[NN];
__device__ int    g_cnt[NN];
__device__ int    g_cursor[NN];
__device__ int    g_startv[NN + 1];
__device__ int    g_csr_rows[EE];
__device__ int    g_bsum[NB];
__device__ int    g_boff[NB];
__device__ float  g_dinv[NN];
__device__ __half g_s[(size_t)NN * HH];      // pre-aggregation messages (fp16, dinv-scaled)
__device__ __half g_ah[(size_t)NN * HIN];    // A operand hi (fp16)
__device__ __half g_al[(size_t)NN * HIN];    // A operand lo (fp16)
__device__ __half g_w16[HH * HIN];           // folded weight fp16, [n][k] K-major
__device__ float  g_sum[HIN];
__device__ float  g_sumsq[HIN];
__device__ float  g_bshift[HH];

// ---------------- PTX helpers (baseline sm_80+ only) ----------------
__device__ __forceinline__ uint32_t smem_u32(const void* p) {
    uint32_t a;
    asm("{ .reg .u64 t; cvta.to.shared.u64 t, %1; cvt.u32.u64 %0, t; }" : "=r"(a) : "l"(p));
    return a;
}
#define CP16(dst, src) \
    asm volatile("cp.async.cg.shared.global [%0], [%1], 16;" :: "r"(dst), "l"(src))
#define CP_COMMIT() asm volatile("cp.async.commit_group;" ::: "memory")
#define CP_WAIT2()  asm volatile("cp.async.wait_group 2;" ::: "memory")
#define LDSM_X4(r, addr) \
    asm volatile("ldmatrix.sync.aligned.m8n8.x4.shared.b16 {%0,%1,%2,%3}, [%4];" \
        : "=r"((r)[0]), "=r"((r)[1]), "=r"((r)[2]), "=r"((r)[3]) : "r"(addr))
#define MMA_F16(c, a, b) \
    asm volatile("mma.sync.aligned.m16n8k16.row.col.f32.f16.f16.f32 " \
        "{%0,%1,%2,%3}, {%4,%5,%6,%7}, {%8,%9}, {%0,%1,%2,%3};" \
        : "+f"((c)[0]), "+f"((c)[1]), "+f"((c)[2]), "+f"((c)[3]) \
        : "r"((a)[0]), "r"((a)[1]), "r"((a)[2]), "r"((a)[3]), "r"((b)[0]), "r"((b)[1]))

// ---------------- CSR build ----------------
__global__ void k_count(const int* __restrict__ ei) {
    int e = blockIdx.x * blockDim.x + threadIdx.x;
    if (e < EE) {
        atomicAdd(&g_degr[ei[e]], 1);
        atomicAdd(&g_cnt[ei[EE + e]], 1);
    }
}

// phase 1: per-block sums of g_cnt
__global__ void k_blocksum() {
    __shared__ int sh[8];
    int i = blockIdx.x * 256 + threadIdx.x;
    int v = (i < NN) ? g_cnt[i] : 0;
    #pragma unroll
    for (int o = 16; o > 0; o >>= 1) v += __shfl_down_sync(0xFFFFFFFFu, v, o);
    if ((threadIdx.x & 31) == 0) sh[threadIdx.x >> 5] = v;
    __syncthreads();
    if (threadIdx.x < 8) {
        int s = sh[threadIdx.x];
        #pragma unroll
        for (int o = 4; o > 0; o >>= 1) s += __shfl_down_sync(0xFFu, s, o);
        if (threadIdx.x == 0) g_bsum[blockIdx.x] = s;
    }
}

// phase 2: exclusive scan of NB block sums (1 block, 256 threads)
__global__ void k_scanb() {
    __shared__ int sh[256];
    int t = threadIdx.x;
    int v = (t < NB) ? g_bsum[t] : 0;
    sh[t] = v;
    __syncthreads();
    #pragma unroll
    for (int o = 1; o < 256; o <<= 1) {
        int u = (t >= o) ? sh[t - o] : 0;
        __syncthreads();
        sh[t] += u;
        __syncthreads();
    }
    if (t < NB) g_boff[t] = sh[t] - v;     // exclusive
    if (t == NB - 1) g_startv[NN] = sh[t]; // total = EE
}

// phase 3: block-local scan + base offset -> g_startv; dinv alongside
__global__ void k_offsets() {
    __shared__ int sh[256];
    int t = threadIdx.x;
    int i = blockIdx.x * 256 + t;
    int v = (i < NN) ? g_cnt[i] : 0;
    sh[t] = v;
    __syncthreads();
    #pragma unroll
    for (int o = 1; o < 256; o <<= 1) {
        int u = (t >= o) ? sh[t - o] : 0;
        __syncthreads();
        sh[t] += u;
        __syncthreads();
    }
    if (i < NN) {
        g_startv[i] = g_boff[blockIdx.x] + sh[t] - v;   // exclusive prefix
        g_dinv[i] = rsqrtf((float)g_degr[i] + 1.0f);
    }
}

__global__ void k_fill(const int* __restrict__ ei) {
    int e = blockIdx.x * blockDim.x + threadIdx.x;
    if (e < EE) {
        int r = ei[e], c = ei[EE + e];
        int p = atomicAdd(&g_cursor[c], 1);
        g_csr_rows[g_startv[c] + p] = r;
    }
}

// ---------------- fused: convert x -> fp16 hi/lo, BN col stats, zero CSR arrays ----------------
__global__ void __launch_bounds__(256) k_convx_stats(const float* __restrict__ x) {
    __shared__ float sS[HIN], sQ[HIN];
    const int t = threadIdx.x;              // 256
    sS[t] = 0.f; sQ[t] = 0.f;
    __syncthreads();

    const int col = (t & 63) * 4;           // fixed 4 columns per thread
    const int ro  = t >> 6;                 // row offset 0..3
    float s0 = 0.f, s1 = 0.f, s2 = 0.f, s3 = 0.f;
    float q0 = 0.f, q1 = 0.f, q2 = 0.f, q3 = 0.f;

    for (int r0 = blockIdx.x * 4; r0 < NN; r0 += gridDim.x * 4) {
        int r = r0 + ro;                    // NN % 4 == 0 -> always < NN
        size_t idx = (size_t)r * HIN + col;
        float4 v = *(const float4*)(x + idx);
        __half h0 = __float2half_rn(v.x), h1 = __float2half_rn(v.y);
        __half h2 = __float2half_rn(v.z), h3 = __float2half_rn(v.w);
        uint2 uh, ul;
        *(__half2*)&uh.x = __halves2half2(h0, h1);
        *(__half2*)&uh.y = __halves2half2(h2, h3);
        *(__half2*)&ul.x = __floats2half2_rn(v.x - __half2float(h0), v.y - __half2float(h1));
        *(__half2*)&ul.y = __floats2half2_rn(v.z - __half2float(h2), v.w - __half2float(h3));
        *(uint2*)(g_ah + idx) = uh;
        *(uint2*)(g_al + idx) = ul;
        s0 += v.x; q0 += v.x * v.x;
        s1 += v.y; q1 += v.y * v.y;
        s2 += v.z; q2 += v.z * v.z;
        s3 += v.w; q3 += v.w * v.w;
    }
    atomicAdd(&sS[col + 0], s0); atomicAdd(&sQ[col + 0], q0);
    atomicAdd(&sS[col + 1], s1); atomicAdd(&sQ[col + 1], q1);
    atomicAdd(&sS[col + 2], s2); atomicAdd(&sQ[col + 2], q2);
    atomicAdd(&sS[col + 3], s3); atomicAdd(&sQ[col + 3], q3);
    __syncthreads();
    atomicAdd(&g_sum[t], sS[t]);
    atomicAdd(&g_sumsq[t], sQ[t]);

    // fused zeroing of CSR count arrays
    for (int i = blockIdx.x * blockDim.x + t; i < NN; i += gridDim.x * blockDim.x) {
        g_degr[i] = 0; g_cnt[i] = 0; g_cursor[i] = 0;
    }
}

// ---------------- fold BN into weights; emit fp16 W^T + fp32 bshift ----------------
__global__ void k_fold(int K, const float* __restrict__ W,
                       const float* __restrict__ gam, const float* __restrict__ bet) {
    __shared__ float sc[HIN], sh[HIN];
    int t = threadIdx.x;             // 256 threads
    if (t < K) {
        float mu  = g_sum[t] * (1.0f / NN);
        float var = g_sumsq[t] * (1.0f / NN) - mu * mu;
        float a   = rsqrtf(var + BNEPS) * gam[t];
        sc[t] = a;
        sh[t] = bet[t] - mu * a;
    }
    __syncthreads();
    for (int idx = t; idx < K * HH; idx += 256) {
        int k = idx >> 7;            // W row
        int n = idx & 127;           // W col
        g_w16[(size_t)n * K + k] = __float2half_rn(sc[k] * W[idx]);
    }
    if (t < HH) {
        float acc = 0.f;
        for (int k = 0; k < K; k++) acc += sh[k] * W[k * HH + t];
        g_bshift[t] = acc;
    }
    g_sum[t] = 0.f;
    g_sumsq[t] = 0.f;
}

// ---------------- 2-term fp16 HMMA GEMM, 3-stage cp.async pipeline ----------------
// g_s(fp16) = ((Ah + Al) @ W16^T + bshift) * dinv[row]
#define RS   48
#define TSZ  (128 * RS)          // 6144 bytes per tile
#define STG  (3 * TSZ)           // 18432 bytes per stage
#define NSTG 3

__global__ void __launch_bounds__(256) k_gemm_h(int K) {
    extern __shared__ char smem[];
    const int t    = threadIdx.x;
    const int wid  = t >> 5;
    const int lane = t & 31;
    const int wm   = wid & 3;          // 32-row band
    const int wn   = wid >> 2;         // 64-col band
    const int row0 = blockIdx.x * 128;
    const uint32_t sbase = smem_u32(smem);

    float c[2][8][4];
    #pragma unroll
    for (int mt = 0; mt < 2; mt++)
        #pragma unroll
        for (int nt = 0; nt < 8; nt++)
            #pragma unroll
            for (int q = 0; q < 4; q++) c[mt][nt][q] = 0.f;

    const int lr = t >> 1;
    const int lh = t & 1;
    const int ar = min(row0 + lr, NN - 1);
    const uint32_t so = lr * RS + lh * 16;
    const int nch = K >> 4;            // >= 8 always

    // prologue: chunks 0,1 -> stages 0,1
    #pragma unroll
    for (int pc = 0; pc < 2; pc++) {
        uint32_t sb = sbase + pc * STG;
        size_t ka = (size_t)ar * K + pc * 16 + lh * 8;
        size_t kb = (size_t)lr * K + pc * 16 + lh * 8;
        CP16(sb + 0 * TSZ + so, g_ah + ka);
        CP16(sb + 1 * TSZ + so, g_al + ka);
        CP16(sb + 2 * TSZ + so, g_w16 + kb);
        CP_COMMIT();
    }

    int stage = 0;
    for (int kc = 0; kc < nch; kc++) {
        int pf = kc + 2;
        if (pf < nch) {
            int ps = pf % NSTG;
            uint32_t sb = sbase + ps * STG;
            size_t ka = (size_t)ar * K + pf * 16 + lh * 8;
            size_t kb = (size_t)lr * K + pf * 16 + lh * 8;
            CP16(sb + 0 * TSZ + so, g_ah + ka);
            CP16(sb + 1 * TSZ + so, g_al + ka);
            CP16(sb + 2 * TSZ + so, g_w16 + kb);
        }
        CP_COMMIT();
        CP_WAIT2();                    // chunk kc's group complete
        __syncthreads();

        uint32_t base = sbase + stage * STG;
        uint32_t ah[2][4], al[2][4];
        #pragma unroll
        for (int mt = 0; mt < 2; mt++) {
            uint32_t addr = base + (wm * 32 + mt * 16 + (lane & 15)) * RS + (lane >> 4) * 16;
            LDSM_X4(ah[mt], addr);
            LDSM_X4(al[mt], addr + TSZ);
        }
        uint32_t bw[8][2];
        #pragma unroll
        for (int p = 0; p < 4; p++) {
            uint32_t addr = base + 2 * TSZ + (wn * 64 + p * 16 + (lane & 15)) * RS + (lane >> 4) * 16;
            uint32_t rr[4];
            LDSM_X4(rr, addr);
            bw[2 * p][0] = rr[0]; bw[2 * p][1] = rr[2];
            bw[2 * p + 1][0] = rr[1]; bw[2 * p + 1][1] = rr[3];
        }
        #pragma unroll
        for (int mt = 0; mt < 2; mt++)
            #pragma unroll
            for (int nt = 0; nt < 8; nt++) {
                MMA_F16(c[mt][nt], ah[mt], bw[nt]);
                MMA_F16(c[mt][nt], al[mt], bw[nt]);
            }
        __syncthreads();               // protect stage reuse by next prefetch
        stage = (stage + 1) % NSTG;
    }

    // epilogue: (acc + bshift[col]) * dinv[row] -> fp16 g_s
    float bsv[8][2];
    #pragma unroll
    for (int nt = 0; nt < 8; nt++) {
        int gc = wn * 64 + nt * 8 + (lane & 3) * 2;
        bsv[nt][0] = __ldg(&g_bshift[gc]);
        bsv[nt][1] = __ldg(&g_bshift[gc + 1]);
    }
    #pragma unroll
    for (int mt = 0; mt < 2; mt++) {
        int r0g = row0 + wm * 32 + mt * 16 + (lane >> 2);
        int r1g = r0g + 8;
        float dv0 = g_dinv[min(r0g, NN - 1)];
        float dv1 = g_dinv[min(r1g, NN - 1)];
        #pragma unroll
        for (int nt = 0; nt < 8; nt++) {
            int gc = wn * 64 + nt * 8 + (lane & 3) * 2;
            if (r0g < NN)
                *(__half2*)(g_s + (size_t)r0g * HH + gc) =
                    __floats2half2_rn((c[mt][nt][0] + bsv[nt][0]) * dv0,
                                      (c[mt][nt][1] + bsv[nt][1]) * dv0);
            if (r1g < NN)
                *(__half2*)(g_s + (size_t)r1g * HH + gc) =
                    __floats2half2_rn((c[mt][nt][2] + bsv[nt][0]) * dv1,
                                      (c[mt][nt][3] + bsv[nt][1]) * dv1);
        }
    }
}

// ---------------- gather: warp-per-node, HADD2 pair-tree, index prefetch ----------------
__global__ void __launch_bounds__(256) k_gather(const float* __restrict__ bgcn,
                                                float* __restrict__ out, int final_layer) {
    const int lane = threadIdx.x & 31;
    const int wg   = (blockIdx.x * blockDim.x + threadIdx.x) >> 5;
    const int nw   = (gridDim.x * blockDim.x) >> 5;
    __shared__ float sS[128], sQ[128];
    if (threadIdx.x < 128) { sS[threadIdx.x] = 0.f; sQ[threadIdx.x] = 0.f; }
    __syncthreads();

    const uint2* __restrict__ s2 = (const uint2*)g_s;   // 32 uint2 per node row
    float4 b = *(const float4*)(bgcn + lane * 4);
    float4 stS = make_float4(0.f, 0.f, 0.f, 0.f);
    float4 stQ = make_float4(0.f, 0.f, 0.f, 0.f);

    for (int node = wg; node < NN; node += nw) {
        uint2 vs = s2[(size_t)node * 32 + lane];        // self-loop (dinv-scaled)
        float2 f0 = __half22float2(*(__half2*)&vs.x);
        float2 f1 = __half22float2(*(__half2*)&vs.y);
        float a0 = f0.x, a1 = f0.y, a2 = f1.x, a3 = f1.y;

        int beg = g_startv[node];
        int end = g_startv[node + 1];
        int k = beg;
        int n0 = 0, n1 = 0, n2 = 0, n3 = 0;
        if (k + 3 < end) {
            n0 = __ldg(&g_csr_rows[k]);
            n1 = __ldg(&g_csr_rows[k + 1]);
            n2 = __ldg(&g_csr_rows[k + 2]);
            n3 = __ldg(&g_csr_rows[k + 3]);
        }
        for (; k + 3 < end; ) {
            int r0 = n0, r1 = n1, r2 = n2, r3 = n3;
            int kn = k + 4;
            if (kn + 3 < end) {        // prefetch next iteration's indices
                n0 = __ldg(&g_csr_rows[kn]);
                n1 = __ldg(&g_csr_rows[kn + 1]);
                n2 = __ldg(&g_csr_rows[kn + 2]);
                n3 = __ldg(&g_csr_rows[kn + 3]);
            }
            uint2 v0 = s2[(size_t)r0 * 32 + lane];
            uint2 v1 = s2[(size_t)r1 * 32 + lane];
            uint2 v2 = s2[(size_t)r2 * 32 + lane];
            uint2 v3 = s2[(size_t)r3 * 32 + lane];
            __half2 p0 = __hadd2(*(__half2*)&v0.x, *(__half2*)&v1.x);
            __half2 p1 = __hadd2(*(__half2*)&v0.y, *(__half2*)&v1.y);
            __half2 p2 = __hadd2(*(__half2*)&v2.x, *(__half2*)&v3.x);
            __half2 p3 = __hadd2(*(__half2*)&v2.y, *(__half2*)&v3.y);
            float2 q;
            q = __half22float2(p0); a0 += q.x; a1 += q.y;
            q = __half22float2(p1); a2 += q.x; a3 += q.y;
            q = __half22float2(p2); a0 += q.x; a1 += q.y;
            q = __half22float2(p3); a2 += q.x; a3 += q.y;
            k = kn;
        }
        if (k + 1 < end) {
            int r0 = __ldg(&g_csr_rows[k]);
            int r1 = __ldg(&g_csr_rows[k + 1]);
            uint2 v0 = s2[(size_t)r0 * 32 + lane];
            uint2 v1 = s2[(size_t)r1 * 32 + lane];
            __half2 p0 = __hadd2(*(__half2*)&v0.x, *(__half2*)&v1.x);
            __half2 p1 = __hadd2(*(__half2*)&v0.y, *(__half2*)&v1.y);
            float2 q;
            q = __half22float2(p0); a0 += q.x; a1 += q.y;
            q = __half22float2(p1); a2 += q.x; a3 += q.y;
            k += 2;
        }
        if (k < end) {
            int r0 = __ldg(&g_csr_rows[k]);
            uint2 v0 = s2[(size_t)r0 * 32 + lane];
            float2 q;
            q = __half22float2(*(__half2*)&v0.x); a0 += q.x; a1 += q.y;
            q = __half22float2(*(__half2*)&v0.y); a2 += q.x; a3 += q.y;
        }

        float dvn = g_dinv[node];
        float4 o;
        o.x = a0 * dvn + b.x;
        o.y = a1 * dvn + b.y;
        o.z = a2 * dvn + b.z;
        o.w = a3 * dvn + b.w;

        if (final_layer) {
            *(float4*)(out + (size_t)node * HH + lane * 4) = o;
        } else {
            __half h0 = __float2half_rn(o.x), h1 = __float2half_rn(o.y);
            __half h2 = __float2half_rn(o.z), h3 = __float2half_rn(o.w);
            size_t base = (size_t)node * HH + lane * 4;
            uint2 uh, ul;
            *(__half2*)&uh.x = __halves2half2(h0, h1);
            *(__half2*)&uh.y = __halves2half2(h2, h3);
            *(__half2*)&ul.x = __floats2half2_rn(o.x - __half2float(h0), o.y - __half2float(h1));
            *(__half2*)&ul.y = __floats2half2_rn(o.z - __half2float(h2), o.w - __half2float(h3));
            *(uint2*)(g_ah + base) = uh;
            *(uint2*)(g_al + base) = ul;
            stS.x += o.x; stS.y += o.y; stS.z += o.z; stS.w += o.w;
            stQ.x += o.x * o.x; stQ.y += o.y * o.y;
            stQ.z += o.z * o.z; stQ.w += o.w * o.w;
        }
    }

    if (!final_layer) {
        atomicAdd(&sS[lane * 4 + 0], stS.x);
        atomicAdd(&sS[lane * 4 + 1], stS.y);
        atomicAdd(&sS[lane * 4 + 2], stS.z);
        atomicAdd(&sS[lane * 4 + 3], stS.w);
        atomicAdd(&sQ[lane * 4 + 0], stQ.x);
        atomicAdd(&sQ[lane * 4 + 1], stQ.y);
        atomicAdd(&sQ[lane * 4 + 2], stQ.z);
        atomicAdd(&sQ[lane * 4 + 3], stQ.w);
        __syncthreads();
        if (threadIdx.x < 128) {
            atomicAdd(&g_sum[threadIdx.x], sS[threadIdx.x]);
            atomicAdd(&g_sumsq[threadIdx.x], sQ[threadIdx.x]);
        }
    }
}

// ---------------- launch ----------------
extern "C" void kernel_launch(void* const* d_in, const int* in_sizes, int n_in,
                              void* d_out, int out_size) {
    const float* x       = (const float*)d_in[0];
    const int*   ei      = (const int*)  d_in[1];
    const float* bnf_g   = (const float*)d_in[2];
    const float* bnf_b   = (const float*)d_in[3];
    const float* W_feat  = (const float*)d_in[4];
    const float* b_feat  = (const float*)d_in[5];
    const float* bn_g    = (const float*)d_in[6];
    const float* bn_b    = (const float*)d_in[7];
    const float* Ws      = (const float*)d_in[8];
    const float* bs      = (const float*)d_in[9];
    float* out = (float*)d_out;

    const int RB = (NN + 127) / 128;              // 391 tiles
    const int GB = 1563;                          // gather: ~12.5k warps
    const int EB = (EE + 255) / 256;
    const int GSM = NSTG * STG;                   // 55296 B dynamic smem

    cudaFuncSetAttribute(k_gemm_h, cudaFuncAttributeMaxDynamicSharedMemorySize, GSM);

    k_convx_stats<<<RB, 256>>>(x);                   // x->fp16 hi/lo + stats + zero CSR
    k_count<<<EB, 256>>>(ei);
    k_fold<<<1, 256>>>(HIN, W_feat, bnf_g, bnf_b);
    k_blocksum<<<NB, 256>>>();                       // parallel scan, phase 1
    k_scanb<<<1, 256>>>();                           // phase 2
    k_offsets<<<NB, 256>>>();                        // phase 3 (+ dinv)
    k_gemm_h<<<RB, 256, GSM>>>(HIN);
    k_fill<<<EB, 256>>>(ei);
    k_gather<<<GB, 256>>>(b_feat, nullptr, 0);

    // 3 GCN layers, K=128
    for (int i = 0; i < 3; i++) {
        k_fold<<<1, 256>>>(HH, Ws + (size_t)i * HH * HH, bn_g + i * HH, bn_b + i * HH);
        k_gemm_h<<<RB, 256, GSM>>>(HH);
        k_gather<<<GB, 256>>>(bs + i * HH, (i == 2) ? out : nullptr, (i == 2) ? 1 : 0);
    }
}

// round 16
// speedup vs baseline: 1.2555x; 1.0423x over previous
#include <cuda_runtime.h>
#include <cuda_fp16.h>
#include <cstdint>

#define NN   50000
#define EE   800000
#define HIN  256
#define HH   128
#define BNEPS 1e-5f
#define NB   196                 // ceil(NN/256)
#define RBC  391                 // ceil(NN/128) gemm/conv tiles
#define EB   3125                // ceil(EE/256)

// ---------------- device scratch ----------------
__device__ int    g_degr[NN];
__device__ int    g_cnt[NN];
__device__ int    g_cursor[NN];
__device__ int    g_startv[NN + 1];
__device__ int    g_csr_rows[EE];
__device__ int    g_bsum[NB];
__device__ int    g_boff[NB];
__device__ float  g_dinv[NN];
__device__ __half g_s[(size_t)NN * HH];      // pre-aggregation messages (fp16, dinv-scaled)
__device__ __half g_ah[(size_t)NN * HIN];    // A operand hi (fp16)
__device__ __half g_al[(size_t)NN * HIN];    // A operand lo (fp16)
__device__ __half g_w16[HH * HIN];           // folded weight fp16, [n][k] K-major
__device__ float  g_sum[HIN];
__device__ float  g_sumsq[HIN];
__device__ float  g_bshift[HH];

// ---------------- PTX helpers (baseline sm_80+ only) ----------------
__device__ __forceinline__ uint32_t smem_u32(const void* p) {
    uint32_t a;
    asm("{ .reg .u64 t; cvta.to.shared.u64 t, %1; cvt.u32.u64 %0, t; }" : "=r"(a) : "l"(p));
    return a;
}
#define CP16(dst, src) \
    asm volatile("cp.async.cg.shared.global [%0], [%1], 16;" :: "r"(dst), "l"(src))
#define CP_COMMIT() asm volatile("cp.async.commit_group;" ::: "memory")
#define CP_WAIT2()  asm volatile("cp.async.wait_group 2;" ::: "memory")
#define LDSM_X4(r, addr) \
    asm volatile("ldmatrix.sync.aligned.m8n8.x4.shared.b16 {%0,%1,%2,%3}, [%4];" \
        : "=r"((r)[0]), "=r"((r)[1]), "=r"((r)[2]), "=r"((r)[3]) : "r"(addr))
#define MMA_F16(c, a, b) \
    asm volatile("mma.sync.aligned.m16n8k16.row.col.f32.f16.f16.f32 " \
        "{%0,%1,%2,%3}, {%4,%5,%6,%7}, {%8,%9}, {%0,%1,%2,%3};" \
        : "+f"((c)[0]), "+f"((c)[1]), "+f"((c)[2]), "+f"((c)[3]) \
        : "r"((a)[0]), "r"((a)[1]), "r"((a)[2]), "r"((a)[3]), "r"((b)[0]), "r"((b)[1]))

// ---------------- zero CSR arrays ----------------
__global__ void k_zero() {
    int i = blockIdx.x * blockDim.x + threadIdx.x;
    if (i < NN) { g_degr[i] = 0; g_cnt[i] = 0; g_cursor[i] = 0; }
}

// ---------------- fat kernel 1: convx+stats (blocks 0..RBC-1) || count (rest) ----------------
__global__ void __launch_bounds__(256) k_conv_count(const float* __restrict__ x,
                                                    const int* __restrict__ ei) {
    __shared__ float sS[HIN], sQ[HIN];
    const int t = threadIdx.x;

    if (blockIdx.x < RBC) {
        sS[t] = 0.f; sQ[t] = 0.f;
        __syncthreads();
        const int col = (t & 63) * 4;
        const int ro  = t >> 6;
        float s0 = 0.f, s1 = 0.f, s2 = 0.f, s3 = 0.f;
        float q0 = 0.f, q1 = 0.f, q2 = 0.f, q3 = 0.f;
        for (int r0 = blockIdx.x * 4; r0 < NN; r0 += RBC * 4) {
            int r = r0 + ro;
            size_t idx = (size_t)r * HIN + col;
            float4 v = *(const float4*)(x + idx);
            __half h0 = __float2half_rn(v.x), h1 = __float2half_rn(v.y);
            __half h2 = __float2half_rn(v.z), h3 = __float2half_rn(v.w);
            uint2 uh, ul;
            *(__half2*)&uh.x = __halves2half2(h0, h1);
            *(__half2*)&uh.y = __halves2half2(h2, h3);
            *(__half2*)&ul.x = __floats2half2_rn(v.x - __half2float(h0), v.y - __half2float(h1));
            *(__half2*)&ul.y = __floats2half2_rn(v.z - __half2float(h2), v.w - __half2float(h3));
            *(uint2*)(g_ah + idx) = uh;
            *(uint2*)(g_al + idx) = ul;
            s0 += v.x; q0 += v.x * v.x;
            s1 += v.y; q1 += v.y * v.y;
            s2 += v.z; q2 += v.z * v.z;
            s3 += v.w; q3 += v.w * v.w;
        }
        atomicAdd(&sS[col + 0], s0); atomicAdd(&sQ[col + 0], q0);
        atomicAdd(&sS[col + 1], s1); atomicAdd(&sQ[col + 1], q1);
        atomicAdd(&sS[col + 2], s2); atomicAdd(&sQ[col + 2], q2);
        atomicAdd(&sS[col + 3], s3); atomicAdd(&sQ[col + 3], q3);
        __syncthreads();
        atomicAdd(&g_sum[t], sS[t]);
        atomicAdd(&g_sumsq[t], sQ[t]);
    } else {
        int e = (blockIdx.x - RBC) * 256 + t;
        if (e < EE) {
            atomicAdd(&g_degr[ei[e]], 1);
            atomicAdd(&g_cnt[ei[EE + e]], 1);
        }
    }
}

// ---------------- parallel scan (3 phases) + dinv ----------------
__global__ void k_blocksum() {
    __shared__ int sh[8];
    int i = blockIdx.x * 256 + threadIdx.x;
    int v = (i < NN) ? g_cnt[i] : 0;
    #pragma unroll
    for (int o = 16; o > 0; o >>= 1) v += __shfl_down_sync(0xFFFFFFFFu, v, o);
    if ((threadIdx.x & 31) == 0) sh[threadIdx.x >> 5] = v;
    __syncthreads();
    if (threadIdx.x < 8) {
        int s = sh[threadIdx.x];
        #pragma unroll
        for (int o = 4; o > 0; o >>= 1) s += __shfl_down_sync(0xFFu, s, o);
        if (threadIdx.x == 0) g_bsum[blockIdx.x] = s;
    }
}
__global__ void k_scanb() {
    __shared__ int sh[256];
    int t = threadIdx.x;
    int v = (t < NB) ? g_bsum[t] : 0;
    sh[t] = v;
    __syncthreads();
    #pragma unroll
    for (int o = 1; o < 256; o <<= 1) {
        int u = (t >= o) ? sh[t - o] : 0;
        __syncthreads();
        sh[t] += u;
        __syncthreads();
    }
    if (t < NB) g_boff[t] = sh[t] - v;
    if (t == NB - 1) g_startv[NN] = sh[t];
}
__global__ void k_offsets() {
    __shared__ int sh[256];
    int t = threadIdx.x;
    int i = blockIdx.x * 256 + t;
    int v = (i < NN) ? g_cnt[i] : 0;
    sh[t] = v;
    __syncthreads();
    #pragma unroll
    for (int o = 1; o < 256; o <<= 1) {
        int u = (t >= o) ? sh[t - o] : 0;
        __syncthreads();
        sh[t] += u;
        __syncthreads();
    }
    if (i < NN) {
        g_startv[i] = g_boff[blockIdx.x] + sh[t] - v;
        g_dinv[i] = rsqrtf((float)g_degr[i] + 1.0f);
    }
}

// ---------------- fold BN into weights; emit fp16 W^T + fp32 bshift ----------------
__global__ void k_fold(int K, const float* __restrict__ W,
                       const float* __restrict__ gam, const float* __restrict__ bet) {
    __shared__ float sc[HIN], sh[HIN];
    int t = threadIdx.x;             // 256 threads
    if (t < K) {
        float mu  = g_sum[t] * (1.0f / NN);
        float var = g_sumsq[t] * (1.0f / NN) - mu * mu;
        float a   = rsqrtf(var + BNEPS) * gam[t];
        sc[t] = a;
        sh[t] = bet[t] - mu * a;
    }
    __syncthreads();
    for (int idx = t; idx < K * HH; idx += 256) {
        int k = idx >> 7;
        int n = idx & 127;
        g_w16[(size_t)n * K + k] = __float2half_rn(sc[k] * W[idx]);
    }
    if (t < HH) {
        float acc = 0.f;
        for (int k = 0; k < K; k++) acc += sh[k] * W[k * HH + t];
        g_bshift[t] = acc;
    }
    g_sum[t] = 0.f;
    g_sumsq[t] = 0.f;
}

// ---------------- 2-term fp16 HMMA GEMM body, 3-stage cp.async pipeline ----------------
#define RS   48
#define TSZ  (128 * RS)          // 6144 bytes per tile
#define STG  (3 * TSZ)           // 18432 bytes per stage
#define NSTG 3

__device__ __forceinline__ void gemm_body(int K, char* smem, int bid) {
    const int t    = threadIdx.x;
    const int wid  = t >> 5;
    const int lane = t & 31;
    const int wm   = wid & 3;
    const int wn   = wid >> 2;
    const int row0 = bid * 128;
    const uint32_t sbase = smem_u32(smem);

    float c[2][8][4];
    #pragma unroll
    for (int mt = 0; mt < 2; mt++)
        #pragma unroll
        for (int nt = 0; nt < 8; nt++)
            #pragma unroll
            for (int q = 0; q < 4; q++) c[mt][nt][q] = 0.f;

    const int lr = t >> 1;
    const int lh = t & 1;
    const int ar = min(row0 + lr, NN - 1);
    const uint32_t so = lr * RS + lh * 16;
    const int nch = K >> 4;

    #pragma unroll
    for (int pc = 0; pc < 2; pc++) {
        uint32_t sb = sbase + pc * STG;
        size_t ka = (size_t)ar * K + pc * 16 + lh * 8;
        size_t kb = (size_t)lr * K + pc * 16 + lh * 8;
        CP16(sb + 0 * TSZ + so, g_ah + ka);
        CP16(sb + 1 * TSZ + so, g_al + ka);
        CP16(sb + 2 * TSZ + so, g_w16 + kb);
        CP_COMMIT();
    }

    int stage = 0;
    for (int kc = 0; kc < nch; kc++) {
        int pf = kc + 2;
        if (pf < nch) {
            int ps = pf % NSTG;
            uint32_t sb = sbase + ps * STG;
            size_t ka = (size_t)ar * K + pf * 16 + lh * 8;
            size_t kb = (size_t)lr * K + pf * 16 + lh * 8;
            CP16(sb + 0 * TSZ + so, g_ah + ka);
            CP16(sb + 1 * TSZ + so, g_al + ka);
            CP16(sb + 2 * TSZ + so, g_w16 + kb);
        }
        CP_COMMIT();
        CP_WAIT2();
        __syncthreads();

        uint32_t base = sbase + stage * STG;
        uint32_t ah[2][4], al[2][4];
        #pragma unroll
        for (int mt = 0; mt < 2; mt++) {
            uint32_t addr = base + (wm * 32 + mt * 16 + (lane & 15)) * RS + (lane >> 4) * 16;
            LDSM_X4(ah[mt], addr);
            LDSM_X4(al[mt], addr + TSZ);
        }
        uint32_t bw[8][2];
        #pragma unroll
        for (int p = 0; p < 4; p++) {
            uint32_t addr = base + 2 * TSZ + (wn * 64 + p * 16 + (lane & 15)) * RS + (lane >> 4) * 16;
            uint32_t rr[4];
            LDSM_X4(rr, addr);
            bw[2 * p][0] = rr[0]; bw[2 * p][1] = rr[2];
            bw[2 * p + 1][0] = rr[1]; bw[2 * p + 1][1] = rr[3];
        }
        #pragma unroll
        for (int mt = 0; mt < 2; mt++)
            #pragma unroll
            for (int nt = 0; nt < 8; nt++) {
                MMA_F16(c[mt][nt], ah[mt], bw[nt]);
                MMA_F16(c[mt][nt], al[mt], bw[nt]);
            }
        __syncthreads();
        stage = (stage + 1) % NSTG;
    }

    float bsv[8][2];
    #pragma unroll
    for (int nt = 0; nt < 8; nt++) {
        int gc = wn * 64 + nt * 8 + (lane & 3) * 2;
        bsv[nt][0] = __ldg(&g_bshift[gc]);
        bsv[nt][1] = __ldg(&g_bshift[gc + 1]);
    }
    #pragma unroll
    for (int mt = 0; mt < 2; mt++) {
        int r0g = row0 + wm * 32 + mt * 16 + (lane >> 2);
        int r1g = r0g + 8;
        float dv0 = g_dinv[min(r0g, NN - 1)];
        float dv1 = g_dinv[min(r1g, NN - 1)];
        #pragma unroll
        for (int nt = 0; nt < 8; nt++) {
            int gc = wn * 64 + nt * 8 + (lane & 3) * 2;
            if (r0g < NN)
                *(__half2*)(g_s + (size_t)r0g * HH + gc) =
                    __floats2half2_rn((c[mt][nt][0] + bsv[nt][0]) * dv0,
                                      (c[mt][nt][1] + bsv[nt][1]) * dv0);
            if (r1g < NN)
                *(__half2*)(g_s + (size_t)r1g * HH + gc) =
                    __floats2half2_rn((c[mt][nt][2] + bsv[nt][0]) * dv1,
                                      (c[mt][nt][3] + bsv[nt][1]) * dv1);
        }
    }
}

__global__ void __launch_bounds__(256) k_gemm_h(int K) {
    extern __shared__ char smem[];
    gemm_body(K, smem, blockIdx.x);
}

// fat kernel 2: gemm (blocks 0..RBC-1) || CSR fill (rest)
__global__ void __launch_bounds__(256) k_gemm_fill(int K, const int* __restrict__ ei) {
    extern __shared__ char smem[];
    if (blockIdx.x < RBC) {
        gemm_body(K, smem, blockIdx.x);
    } else {
        int e = (blockIdx.x - RBC) * 256 + threadIdx.x;
        if (e < EE) {
            int r = ei[e], c = ei[EE + e];
            int p = atomicAdd(&g_cursor[c], 1);
            g_csr_rows[g_startv[c] + p] = r;
        }
    }
}

// ---------------- gather: warp-per-node, HADD2 pair-tree, index prefetch ----------------
__global__ void __launch_bounds__(256) k_gather(const float* __restrict__ bgcn,
                                                float* __restrict__ out, int final_layer) {
    const int lane = threadIdx.x & 31;
    const int wg   = (blockIdx.x * blockDim.x + threadIdx.x) >> 5;
    const int nw   = (gridDim.x * blockDim.x) >> 5;
    __shared__ float sS[128], sQ[128];
    if (threadIdx.x < 128) { sS[threadIdx.x] = 0.f; sQ[threadIdx.x] = 0.f; }
    __syncthreads();

    const uint2* __restrict__ s2 = (const uint2*)g_s;
    float4 b = *(const float4*)(bgcn + lane * 4);
    float4 stS = make_float4(0.f, 0.f, 0.f, 0.f);
    float4 stQ = make_float4(0.f, 0.f, 0.f, 0.f);

    for (int node = wg; node < NN; node += nw) {
        uint2 vs = s2[(size_t)node * 32 + lane];
        float2 f0 = __half22float2(*(__half2*)&vs.x);
        float2 f1 = __half22float2(*(__half2*)&vs.y);
        float a0 = f0.x, a1 = f0.y, a2 = f1.x, a3 = f1.y;

        int beg = g_startv[node];
        int end = g_startv[node + 1];
        int k = beg;
        int n0 = 0, n1 = 0, n2 = 0, n3 = 0;
        if (k + 3 < end) {
            n0 = __ldg(&g_csr_rows[k]);
            n1 = __ldg(&g_csr_rows[k + 1]);
            n2 = __ldg(&g_csr_rows[k + 2]);
            n3 = __ldg(&g_csr_rows[k + 3]);
        }
        for (; k + 3 < end; ) {
            int r0 = n0, r1 = n1, r2 = n2, r3 = n3;
            int kn = k + 4;
            if (kn + 3 < end) {
                n0 = __ldg(&g_csr_rows[kn]);
                n1 = __ldg(&g_csr_rows[kn + 1]);
                n2 = __ldg(&g_csr_rows[kn + 2]);
                n3 = __ldg(&g_csr_rows[kn + 3]);
            }
            uint2 v0 = s2[(size_t)r0 * 32 + lane];
            uint2 v1 = s2[(size_t)r1 * 32 + lane];
            uint2 v2 = s2[(size_t)r2 * 32 + lane];
            uint2 v3 = s2[(size_t)r3 * 32 + lane];
            __half2 p0 = __hadd2(*(__half2*)&v0.x, *(__half2*)&v1.x);
            __half2 p1 = __hadd2(*(__half2*)&v0.y, *(__half2*)&v1.y);
            __half2 p2 = __hadd2(*(__half2*)&v2.x, *(__half2*)&v3.x);
            __half2 p3 = __hadd2(*(__half2*)&v2.y, *(__half2*)&v3.y);
            float2 q;
            q = __half22float2(p0); a0 += q.x; a1 += q.y;
            q = __half22float2(p1); a2 += q.x; a3 += q.y;
            q = __half22float2(p2); a0 += q.x; a1 += q.y;
            q = __half22float2(p3); a2 += q.x; a3 += q.y;
            k = kn;
        }
        if (k + 1 < end) {
            int r0 = __ldg(&g_csr_rows[k]);
            int r1 = __ldg(&g_csr_rows[k + 1]);
            uint2 v0 = s2[(size_t)r0 * 32 + lane];
            uint2 v1 = s2[(size_t)r1 * 32 + lane];
            __half2 p0 = __hadd2(*(__half2*)&v0.x, *(__half2*)&v1.x);
            __half2 p1 = __hadd2(*(__half2*)&v0.y, *(__half2*)&v1.y);
            float2 q;
            q = __half22float2(p0); a0 += q.x; a1 += q.y;
            q = __half22float2(p1); a2 += q.x; a3 += q.y;
            k += 2;
        }
        if (k < end) {
            int r0 = __ldg(&g_csr_rows[k]);
            uint2 v0 = s2[(size_t)r0 * 32 + lane];
            float2 q;
            q = __half22float2(*(__half2*)&v0.x); a0 += q.x; a1 += q.y;
            q = __half22float2(*(__half2*)&v0.y); a2 += q.x; a3 += q.y;
        }

        float dvn = g_dinv[node];
        float4 o;
        o.x = a0 * dvn + b.x;
        o.y = a1 * dvn + b.y;
        o.z = a2 * dvn + b.z;
        o.w = a3 * dvn + b.w;

        if (final_layer) {
            *(float4*)(out + (size_t)node * HH + lane * 4) = o;
        } else {
            __half h0 = __float2half_rn(o.x), h1 = __float2half_rn(o.y);
            __half h2 = __float2half_rn(o.z), h3 = __float2half_rn(o.w);
            size_t base = (size_t)node * HH + lane * 4;
            uint2 uh, ul;
            *(__half2*)&uh.x = __halves2half2(h0, h1);
            *(__half2*)&uh.y = __halves2half2(h2, h3);
            *(__half2*)&ul.x = __floats2half2_rn(o.x - __half2float(h0), o.y - __half2float(h1));
            *(__half2*)&ul.y = __floats2half2_rn(o.z - __half2float(h2), o.w - __half2float(h3));
            *(uint2*)(g_ah + base) = uh;
            *(uint2*)(g_al + base) = ul;
            stS.x += o.x; stS.y += o.y; stS.z += o.z; stS.w += o.w;
            stQ.x += o.x * o.x; stQ.y += o.y * o.y;
            stQ.z += o.z * o.z; stQ.w += o.w * o.w;
        }
    }

    if (!final_layer) {
        atomicAdd(&sS[lane * 4 + 0], stS.x);
        atomicAdd(&sS[lane * 4 + 1], stS.y);
        atomicAdd(&sS[lane * 4 + 2], stS.z);
        atomicAdd(&sS[lane * 4 + 3], stS.w);
        atomicAdd(&sQ[lane * 4 + 0], stQ.x);
        atomicAdd(&sQ[lane * 4 + 1], stQ.y);
        atomicAdd(&sQ[lane * 4 + 2], stQ.z);
        atomicAdd(&sQ[lane * 4 + 3], stQ.w);
        __syncthreads();
        if (threadIdx.x < 128) {
            atomicAdd(&g_sum[threadIdx.x], sS[threadIdx.x]);
            atomicAdd(&g_sumsq[threadIdx.x], sQ[threadIdx.x]);
        }
    }
}

// ---------------- launch ----------------
extern "C" void kernel_launch(void* const* d_in, const int* in_sizes, int n_in,
                              void* d_out, int out_size) {
    const float* x       = (const float*)d_in[0];
    const int*   ei      = (const int*)  d_in[1];
    const float* bnf_g   = (const float*)d_in[2];
    const float* bnf_b   = (const float*)d_in[3];
    const float* W_feat  = (const float*)d_in[4];
    const float* b_feat  = (const float*)d_in[5];
    const float* bn_g    = (const float*)d_in[6];
    const float* bn_b    = (const float*)d_in[7];
    const float* Ws      = (const float*)d_in[8];
    const float* bs      = (const float*)d_in[9];
    float* out = (float*)d_out;

    const int GB  = 1563;                         // gather blocks
    const int GSM = NSTG * STG;                   // 55296 B dynamic smem

    cudaFuncSetAttribute(k_gemm_h,    cudaFuncAttributeMaxDynamicSharedMemorySize, GSM);
    cudaFuncSetAttribute(k_gemm_fill, cudaFuncAttributeMaxDynamicSharedMemorySize, GSM);

    k_zero<<<NB, 256>>>();                           // zero CSR arrays
    k_conv_count<<<RBC + EB, 256>>>(x, ei);          // convx+stats || edge count
    k_fold<<<1, 256>>>(HIN, W_feat, bnf_g, bnf_b);
    k_blocksum<<<NB, 256>>>();                       // scan phase 1
    k_scanb<<<1, 256>>>();                           // phase 2
    k_offsets<<<NB, 256>>>();                        // phase 3 (+ dinv)
    k_gemm_fill<<<RBC + EB, 256, GSM>>>(HIN, ei);    // GEMM K=256 || CSR fill
    k_gather<<<GB, 256>>>(b_feat, nullptr, 0);

    // 3 GCN layers, K=128
    for (int i = 0; i < 3; i++) {
        k_fold<<<1, 256>>>(HH, Ws + (size_t)i * HH * HH, bn_g + i * HH, bn_b + i * HH);
        k_gemm_h<<<RBC, 256, GSM>>>(HH);
        k_gather<<<GB, 256>>>(bs + i * HH, (i == 2) ? out : nullptr, (i == 2) ? 1 : 0);
    }
}